// round 16
// baseline (speedup 1.0000x reference)
#include <cuda_runtime.h>
#include <cuda_bf16.h>
#include <cuda_fp16.h>
#include <cstdint>
#include <cstddef>

// Problem constants
#define BB    8
#define SQ    4096
#define QD    1280
#define SCTX  93
#define CD    2048
#define NH    20
#define DH    64
#define INNER 1280

// ---------------------------------------------------------------------------
// Scratch (__device__ globals; no allocs allowed)
// ---------------------------------------------------------------------------
__device__ __align__(16) unsigned char g_qt[(size_t)BB * NH * 32 * 16384];
__device__ __align__(16) unsigned char g_kt[(size_t)BB * NH * 12288];
__device__ __align__(16) unsigned char g_vt[(size_t)BB * NH * 13312];

__device__ __half g_x16 [(size_t)BB * SQ * QD];
__device__ __half g_a16 [(size_t)BB * SQ * INNER];
__device__ __half g_wq16[(size_t)INNER * QD];
__device__ __half g_wo16[(size_t)QD * INNER];
__device__ float  g_k[(size_t)BB * NH * SCTX * DH];
__device__ float  g_v[(size_t)BB * NH * SCTX * DH];

// ---------------------------------------------------------------------------
// Helpers (arch-agnostic PTX only: cp.async, ldmatrix, mma.sync)
// ---------------------------------------------------------------------------
__device__ __forceinline__ uint32_t smem_u32(const void* p) {
    uint32_t a;
    asm("{ .reg .u64 t; cvta.to.shared.u64 t, %1; cvt.u32.u64 %0, t; }"
        : "=r"(a) : "l"(p));
    return a;
}
#define CP_COMMIT() asm volatile("cp.async.commit_group;" ::: "memory")
#define CP_WAIT(n)  asm volatile("cp.async.wait_group %0;" :: "n"(n) : "memory")
#define CP_ASYNC16(dst, src) \
    asm volatile("cp.async.cg.shared.global [%0], [%1], 16;" \
                 :: "r"(dst), "l"(src) : "memory")

__device__ __forceinline__ void ldsm_x4(uint32_t addr, uint32_t& r0, uint32_t& r1,
                                        uint32_t& r2, uint32_t& r3) {
    asm volatile("ldmatrix.sync.aligned.m8n8.x4.shared.b16 {%0,%1,%2,%3}, [%4];"
                 : "=r"(r0), "=r"(r1), "=r"(r2), "=r"(r3) : "r"(addr));
}
__device__ __forceinline__ void mma_fp16(float* c, const uint32_t* a,
                                         const uint32_t* b) {
    asm volatile(
        "mma.sync.aligned.m16n8k16.row.col.f32.f16.f16.f32 "
        "{%0,%1,%2,%3}, {%4,%5,%6,%7}, {%8,%9}, {%0,%1,%2,%3};"
        : "+f"(c[0]), "+f"(c[1]), "+f"(c[2]), "+f"(c[3])
        : "r"(a[0]), "r"(a[1]), "r"(a[2]), "r"(a[3]), "r"(b[0]), "r"(b[1]));
}
__device__ __forceinline__ uint32_t packhf(float x, float y) {
    __half2 t = __floats2half2_rn(x, y);
    return *(uint32_t*)&t;
}

// ---------------------------------------------------------------------------
// Single-launch fp32 -> fp16 cast for x, Wq, Wout (block-range dispatch)
// ---------------------------------------------------------------------------
#define NXB 4096
#define NWB 200
__global__ void __launch_bounds__(256) to_fp16_all(
    const float4* __restrict__ x,  ushort4* __restrict__ x16,
    const float4* __restrict__ wq, ushort4* __restrict__ wq16,
    const float4* __restrict__ wo, ushort4* __restrict__ wo16)
{
    const float4* src;
    ushort4* dst;
    int n4, bid, nb;
    if (blockIdx.x < NXB) {
        src = x;  dst = x16;  n4 = (int)((size_t)BB * SQ * QD / 4);
        bid = blockIdx.x; nb = NXB;
    } else if (blockIdx.x < NXB + NWB) {
        src = wq; dst = wq16; n4 = INNER * QD / 4;
        bid = blockIdx.x - NXB; nb = NWB;
    } else {
        src = wo; dst = wo16; n4 = QD * INNER / 4;
        bid = blockIdx.x - NXB - NWB; nb = NWB;
    }
    for (int i = bid * 256 + threadIdx.x; i < n4; i += nb * 256) {
        float4 v = src[i];
        ushort4 o;
        o.x = __half_as_ushort(__float2half_rn(v.x));
        o.y = __half_as_ushort(__float2half_rn(v.y));
        o.z = __half_as_ushort(__float2half_rn(v.z));
        o.w = __half_as_ushort(__float2half_rn(v.w));
        dst[i] = o;
    }
}

// ---------------------------------------------------------------------------
// KV projection + pack, fused (validated in R11-R15).
// ---------------------------------------------------------------------------
__global__ void __launch_bounds__(512) kv_proj_pack(
    const float* __restrict__ ctx,
    const float* __restrict__ Wk,  const float* __restrict__ Wv,
    const float* __restrict__ Wki, const float* __restrict__ Wvi,
    const int*   __restrict__ nimg_p)
{
    __shared__ float cs[96][17];
    __shared__ float wk_s[64][17], wv_s[64][17], wki_s[64][17], wvi_s[64][17];

    const int tid = threadIdx.x;
    const int b   = blockIdx.y;
    const int hh  = blockIdx.x;
    const int n0  = hh * 64;
    const int eos = SCTX - *nimg_p;
    const int n   = tid & 63;
    const int g   = tid >> 6;
    const int bh  = b * NH + hh;

    float ak[12], av[12];
#pragma unroll
    for (int j = 0; j < 12; ++j) { ak[j] = 0.f; av[j] = 0.f; }

    for (int k0 = 0; k0 < CD; k0 += 16) {
        __syncthreads();
        for (int i = tid; i < 96 * 16; i += 512) {
            int s = i >> 4, kk = i & 15;
            cs[s][kk] = (s < SCTX) ? ctx[((size_t)b * SCTX + s) * CD + k0 + kk] : 0.f;
        }
        for (int i = tid; i < 64 * 16; i += 512) {
            int r = i >> 4, kk = i & 15;
            size_t gi = (size_t)(n0 + r) * CD + k0 + kk;
            wk_s [r][kk] = Wk [gi]; wv_s [r][kk] = Wv [gi];
            wki_s[r][kk] = Wki[gi]; wvi_s[r][kk] = Wvi[gi];
        }
        __syncthreads();
#pragma unroll
        for (int kk = 0; kk < 16; ++kk) {
            float wkv = wk_s[n][kk],  wvv = wv_s[n][kk];
            float wkiv = wki_s[n][kk], wviv = wvi_s[n][kk];
#pragma unroll
            for (int j = 0; j < 12; ++j) {
                int s = g * 12 + j;
                float c = cs[s][kk];
                bool txt = (s < eos);
                ak[j] = fmaf(c, txt ? wkv : wkiv, ak[j]);
                av[j] = fmaf(c, txt ? wvv : wviv, av[j]);
            }
        }
    }
    size_t base = ((size_t)bh * SCTX) * DH + n;
#pragma unroll
    for (int j = 0; j < 12; ++j) {
        int s = g * 12 + j;
        if (s < SCTX) {
            g_k[base + (size_t)s * DH] = ak[j];
            g_v[base + (size_t)s * DH] = av[j];
        }
    }
    __syncthreads();

    // pack K: 96 rows x 128B swizzled fp16
    for (int idx = tid; idx < 96 * 8; idx += 512) {
        int r = idx >> 3, cb = idx & 7;
        float4 u = {0,0,0,0}, v = {0,0,0,0};
        if (r < SCTX) {
            const float4* kp = (const float4*)(g_k + ((size_t)bh * SCTX + r) * DH + cb * 8);
            u = kp[0]; v = kp[1];
        }
        uint4 H;
        H.x = packhf(u.x, u.y); H.y = packhf(u.z, u.w);
        H.z = packhf(v.x, v.y); H.w = packhf(v.z, v.w);
        size_t off = (size_t)bh * 12288 + r * 128 + ((cb ^ (r & 7)) << 4);
        *(uint4*)(g_kt + off) = H;
    }
    // pack Vt: 64 rows(d) x 208B stride fp16
    for (int idx = tid; idx < 64 * 12; idx += 512) {
        int d = idx / 12, sc = idx % 12;
        float vals[8];
#pragma unroll
        for (int j = 0; j < 8; ++j) {
            int s = sc * 8 + j;
            vals[j] = (s < SCTX) ? g_v[((size_t)bh * SCTX + s) * DH + d] : 0.f;
        }
        uint4 H;
        H.x = packhf(vals[0], vals[1]); H.y = packhf(vals[2], vals[3]);
        H.z = packhf(vals[4], vals[5]); H.w = packhf(vals[6], vals[7]);
        size_t off = (size_t)bh * 13312 + d * 208 + sc * 16;
        *(uint4*)(g_vt + off) = H;
    }
}

// ---------------------------------------------------------------------------
// fp16 HMMA GEMM (R8 config; REMAP_Q epilogue pre-scales Q by 1/sqrt(64)).
// ---------------------------------------------------------------------------
#define GEMM_STAGES 3
#define TILE_BYTES  16384
#define STAGE_BYTES (2 * TILE_BYTES)
#define GEMM_SMEM   (GEMM_STAGES * STAGE_BYTES)

__device__ __forceinline__ void load_tiles16(
    uint32_t sbase,
    const __half* __restrict__ A, const __half* __restrict__ B,
    int m0, int n0, int k0, int K, int tid)
{
#pragma unroll
    for (int i = 0; i < 8; ++i) {
        int idx = tid + (i << 8);
        int mat = idx >> 10;
        int r   = (idx >> 3) & 127;
        int cb  = idx & 7;
        int grow = ((mat == 0) ? m0 : n0) + r;
        const __half* base = (mat == 0) ? A : B;
        const char* src = (const char*)(base + (size_t)grow * K + k0) + (cb << 4);
        uint32_t dst = sbase + (mat << 14) + (r << 7)
                     + (uint32_t)((cb ^ (r & 7)) << 4);
        CP_ASYNC16(dst, src);
    }
}

template <bool REMAP_Q, bool HAS_BIAS>
__global__ void __launch_bounds__(256, 2) gemm_fp16(
    const __half* __restrict__ A, const __half* __restrict__ B,
    const float* __restrict__ bias, float* __restrict__ C, int K)
{
    extern __shared__ __align__(128) char smem[];
    const uint32_t sb = smem_u32(smem);
    const int tid  = threadIdx.x;
    const int wid  = tid >> 5;
    const int lane = tid & 31;
    const int mw   = wid >> 2;
    const int nw   = wid & 3;
    const int n0   = blockIdx.x << 7;
    const int m0   = blockIdx.y << 7;
    const int NCH  = K >> 6;

    uint32_t arow[4];
#pragma unroll
    for (int mi = 0; mi < 4; ++mi)
        arow[mi] = (uint32_t)(mw * 64 + mi * 16 + (lane & 15));
    uint32_t brow[2];
#pragma unroll
    for (int bt = 0; bt < 2; ++bt)
        brow[bt] = (uint32_t)(nw * 32 + bt * 16 + ((lane >> 4) << 3) + (lane & 7));
    const uint32_t cA = (uint32_t)(lane >> 4) << 4;
    const uint32_t cB = ((uint32_t)(lane >> 3) & 1) << 4;

    float acc[4][4][4];
#pragma unroll
    for (int i = 0; i < 4; ++i)
#pragma unroll
        for (int j = 0; j < 4; ++j)
#pragma unroll
            for (int v = 0; v < 4; ++v) acc[i][j][v] = 0.f;

#pragma unroll
    for (int c = 0; c < GEMM_STAGES - 1; ++c) {
        load_tiles16(sb + c * STAGE_BYTES, A, B, m0, n0, c << 6, K, tid);
        CP_COMMIT();
    }

    int s = 0;
    for (int c = 0; c < NCH; ++c) {
        CP_WAIT(1);
        __syncthreads();

        if (c + GEMM_STAGES - 1 < NCH) {
            int sn = c + GEMM_STAGES - 1;
            load_tiles16(sb + (sn % GEMM_STAGES) * STAGE_BYTES, A, B,
                         m0, n0, sn << 6, K, tid);
        }
        CP_COMMIT();

        const uint32_t bA = sb + s * STAGE_BYTES;
        const uint32_t bB = bA + TILE_BYTES;

#pragma unroll
        for (int t = 0; t < 4; ++t) {
            uint32_t a[4][4], b[4][2];
#pragma unroll
            for (int mi = 0; mi < 4; ++mi) {
                uint32_t byte = arow[mi] * 128
                    + (((uint32_t)(t * 32) + cA) ^ ((arow[mi] & 7) << 4));
                ldsm_x4(bA + byte, a[mi][0], a[mi][1], a[mi][2], a[mi][3]);
            }
#pragma unroll
            for (int bt = 0; bt < 2; ++bt) {
                uint32_t byte = brow[bt] * 128
                    + (((uint32_t)(t * 32) + cB) ^ ((brow[bt] & 7) << 4));
                ldsm_x4(bB + byte, b[bt*2][0], b[bt*2][1],
                                   b[bt*2+1][0], b[bt*2+1][1]);
            }
#pragma unroll
            for (int mi = 0; mi < 4; ++mi)
#pragma unroll
                for (int ni = 0; ni < 4; ++ni)
                    mma_fp16(acc[mi][ni], a[mi], b[ni]);
        }
        s = (s == GEMM_STAGES - 1) ? 0 : s + 1;
    }

    // epilogue
#pragma unroll
    for (int mi = 0; mi < 4; ++mi) {
        const int mbase = m0 + mw * 64 + mi * 16 + (lane >> 2);
#pragma unroll
        for (int ni = 0; ni < 4; ++ni) {
            const int n = n0 + nw * 32 + ni * 8 + (lane & 3) * 2;
            if (REMAP_Q) {
                const int h = n >> 6, d = n & 63;
#pragma unroll
                for (int rr = 0; rr < 2; ++rr) {
                    const int m  = mbase + rr * 8;
                    const int b_ = m >> 12, sq = m & 4095;
                    const int qt = sq >> 7,  r  = sq & 127;
                    const int bh = b_ * NH + h;
                    size_t off = ((size_t)(bh * 32 + qt)) * 16384
                               + r * 128 + (((d >> 3) ^ (r & 7)) << 4)
                               + (d & 7) * 2;
                    *(uint32_t*)(g_qt + off) =
                        packhf(acc[mi][ni][rr * 2] * 0.125f,
                               acc[mi][ni][rr * 2 + 1] * 0.125f);
                }
            } else {
                float2 v0, v1;
                v0.x = acc[mi][ni][0]; v0.y = acc[mi][ni][1];
                v1.x = acc[mi][ni][2]; v1.y = acc[mi][ni][3];
                if (HAS_BIAS) {
                    float b0 = bias[n], b1 = bias[n + 1];
                    v0.x += b0; v0.y += b1; v1.x += b0; v1.y += b1;
                }
                *(float2*)(C + (size_t)mbase * QD + n) = v0;
                *(float2*)(C + (size_t)(mbase + 8) * QD + n) = v1;
            }
        }
    }
}

// ---------------------------------------------------------------------------
// fp16 flash attention, register-lean v4:
// - sequential m-tiles, interleaved ldsm/MMA, single-exp softmax (R15)
// - pass-A SCTX mask specialized to j==11 (cols 88-95 are the only ones
//   that can exceed SCTX=93; j<=10 => col <= 87).
// ---------------------------------------------------------------------------
#define AQ  0
#define AK  16384
#define AV  28672
#define ATTN_SMEM 41984

__global__ void __launch_bounds__(128, 5) attn_mma(
    const float* __restrict__ scale_p, const int* __restrict__ nimg_p)
{
    extern __shared__ __align__(128) char smem[];
    const uint32_t sb = smem_u32(smem);
    const int tid  = threadIdx.x;
    const int lane = tid & 31;
    const int w    = tid >> 5;
    const int bh   = blockIdx.x;
    const int qt   = blockIdx.y;
    const int q0   = qt << 7;
    const int b    = bh / NH;
    const int h    = bh % NH;
    const int eos  = SCTX - *nimg_p;
    const float ipscale = *scale_p;

    {
        const unsigned char* qb = g_qt + ((size_t)(bh * 32 + qt)) * 16384;
        for (uint32_t o = tid * 16; o < 16384; o += 2048)
            CP_ASYNC16(sb + AQ + o, qb + o);
        const unsigned char* kb = g_kt + (size_t)bh * 12288;
        for (uint32_t o = tid * 16; o < 12288; o += 2048)
            CP_ASYNC16(sb + AK + o, kb + o);
        const unsigned char* vb = g_vt + (size_t)bh * 13312;
        for (uint32_t o = tid * 16; o < 13312; o += 2048)
            CP_ASYNC16(sb + AV + o, vb + o);
    }
    CP_COMMIT();
    CP_WAIT(0);
    __syncthreads();

    const int c0 = 2 * (lane & 3);

#pragma unroll
    for (int mi = 0; mi < 2; ++mi) {
        // ---- QK^T for this 16-row tile (ldsm interleaved with MMA) ----
        float Lg[12][4];
#pragma unroll
        for (int j = 0; j < 12; ++j)
#pragma unroll
            for (int v = 0; v < 4; ++v) Lg[j][v] = 0.f;

#pragma unroll
        for (int kc = 0; kc < 4; ++kc) {
            uint32_t qa[4];
            {
                uint32_t row = (uint32_t)(w * 32 + mi * 16 + (lane & 15));
                uint32_t byte = row * 128
                    + (((uint32_t)(kc * 32) + ((uint32_t)(lane >> 4) << 4))
                       ^ ((row & 7) << 4));
                ldsm_x4(sb + AQ + byte, qa[0], qa[1], qa[2], qa[3]);
            }
#pragma unroll
            for (int bt = 0; bt < 6; ++bt) {
                uint32_t row = (uint32_t)(bt * 16 + ((lane >> 4) << 3) + (lane & 7));
                uint32_t byte = row * 128
                    + (((uint32_t)(kc * 32) + (((uint32_t)(lane >> 3) & 1) << 4))
                       ^ ((row & 7) << 4));
                uint32_t k0a, k0b, k1a, k1b;
                ldsm_x4(sb + AK + byte, k0a, k0b, k1a, k1b);
                uint32_t kb0[2] = {k0a, k0b};
                uint32_t kb1[2] = {k1a, k1b};
                mma_fp16(Lg[bt * 2],     qa, kb0);
                mma_fp16(Lg[bt * 2 + 1], qa, kb1);
            }
        }

        // ---- two-segment softmax (single-exp; mask only j==11) ----
#pragma unroll
        for (int half = 0; half < 2; ++half) {
            // pass A: mask invalid cols (only possible in j==11), segment maxes
            float mx1 = -1e30f, mx2 = -1e30f;
#pragma unroll
            for (int j = 0; j < 12; ++j)
#pragma unroll
                for (int u = 0; u < 2; ++u) {
                    int col = j * 8 + c0 + u;
                    float v = Lg[j][half * 2 + u];
                    if (j == 11) {                    // compile-time branch
                        if (col >= SCTX) { v = -1e30f; Lg[j][half * 2 + u] = v; }
                    }
                    if (col < eos) mx1 = fmaxf(mx1, v);
                    else           mx2 = fmaxf(mx2, v);
                }
            mx1 = fmaxf(mx1, __shfl_xor_sync(0xffffffffu, mx1, 1));
            mx1 = fmaxf(mx1, __shfl_xor_sync(0xffffffffu, mx1, 2));
            mx2 = fmaxf(mx2, __shfl_xor_sync(0xffffffffu, mx2, 1));
            mx2 = fmaxf(mx2, __shfl_xor_sync(0xffffffffu, mx2, 2));
            // pass B: e = exp(v - mx_sel) once; store into Lg; accumulate sums
            float s1 = 0.f, s2 = 0.f;
#pragma unroll
            for (int j = 0; j < 12; ++j)
#pragma unroll
                for (int u = 0; u < 2; ++u) {
                    int col = j * 8 + c0 + u;
                    bool t = (col < eos);
                    float e = __expf(Lg[j][half * 2 + u] - (t ? mx1 : mx2));
                    Lg[j][half * 2 + u] = e;
                    if (t) s1 += e; else s2 += e;
                }
            s1 += __shfl_xor_sync(0xffffffffu, s1, 1);
            s1 += __shfl_xor_sync(0xffffffffu, s1, 2);
            s2 += __shfl_xor_sync(0xffffffffu, s2, 1);
            s2 += __shfl_xor_sync(0xffffffffu, s2, 2);
            float w1 = (s1 > 0.f) ? 1.f / s1 : 0.f;
            float w2 = (s2 > 0.f) ? ipscale / s2 : 0.f;
            // pass C: scale stored exps by segment weight
#pragma unroll
            for (int j = 0; j < 12; ++j)
#pragma unroll
                for (int u = 0; u < 2; ++u) {
                    int col = j * 8 + c0 + u;
                    Lg[j][half * 2 + u] *= (col < eos) ? w1 : w2;
                }
        }

        // ---- P * V for this tile (ldsm interleaved with MMA) ----
        float o[8][4];
#pragma unroll
        for (int nd = 0; nd < 8; ++nd)
#pragma unroll
            for (int v = 0; v < 4; ++v) o[nd][v] = 0.f;

#pragma unroll
        for (int kc = 0; kc < 6; ++kc) {
            const float* p0 = Lg[2 * kc];
            const float* p1 = Lg[2 * kc + 1];
            uint32_t pa[4];
            pa[0] = packhf(p0[0], p0[1]);
            pa[1] = packhf(p0[2], p0[3]);
            pa[2] = packhf(p1[0], p1[1]);
            pa[3] = packhf(p1[2], p1[3]);
#pragma unroll
            for (int dt = 0; dt < 4; ++dt) {
                uint32_t row = (uint32_t)(dt * 16 + ((lane >> 4) << 3) + (lane & 7));
                uint32_t byte = row * 208 + (uint32_t)(kc * 32)
                              + (((uint32_t)(lane >> 3) & 1) << 4);
                uint32_t v0a, v0b, v1a, v1b;
                ldsm_x4(sb + AV + byte, v0a, v0b, v1a, v1b);
                uint32_t vb0[2] = {v0a, v0b};
                uint32_t vb1[2] = {v1a, v1b};
                mma_fp16(o[dt * 2],     pa, vb0);
                mma_fp16(o[dt * 2 + 1], pa, vb1);
            }
        }

        // ---- store this tile ----
        const int r0 = q0 + w * 32 + mi * 16 + (lane >> 2);
#pragma unroll
        for (int nd = 0; nd < 8; ++nd) {
            const int d = nd * 8 + c0;
            size_t base0 = ((size_t)b * SQ + r0) * INNER + h * DH + d;
            size_t base1 = base0 + (size_t)8 * INNER;
            *(uint32_t*)(g_a16 + base0) = packhf(o[nd][0], o[nd][1]);
            *(uint32_t*)(g_a16 + base1) = packhf(o[nd][2], o[nd][3]);
        }
    }
}

// ---------------------------------------------------------------------------
// Launch: x, context, scale, num_img_token, Wq, Wk, Wv, Wk_ip, Wv_ip, Wout, b_out
// ---------------------------------------------------------------------------
extern "C" void kernel_launch(void* const* d_in, const int* in_sizes, int n_in,
                              void* d_out, int out_size)
{
    const float* x     = (const float*)d_in[0];
    const float* ctx   = (const float*)d_in[1];
    const float* scale = (const float*)d_in[2];
    const int*   nimg  = (const int*)  d_in[3];
    const float* Wq    = (const float*)d_in[4];
    const float* Wout  = (const float*)d_in[9];
    const float* bout  = (const float*)d_in[10];
    float*       out   = (float*)d_out;

    __half *x16, *a16, *wq16, *wo16;
    cudaGetSymbolAddress((void**)&x16,  g_x16);
    cudaGetSymbolAddress((void**)&a16,  g_a16);
    cudaGetSymbolAddress((void**)&wq16, g_wq16);
    cudaGetSymbolAddress((void**)&wo16, g_wo16);

    cudaFuncSetAttribute(attn_mma,
        cudaFuncAttributeMaxDynamicSharedMemorySize, ATTN_SMEM);
    cudaFuncSetAttribute(gemm_fp16<true, false>,
        cudaFuncAttributeMaxDynamicSharedMemorySize, GEMM_SMEM);
    cudaFuncSetAttribute(gemm_fp16<false, true>,
        cudaFuncAttributeMaxDynamicSharedMemorySize, GEMM_SMEM);

    // conversions (single launch for x, Wq, Wout)
    to_fp16_all<<<NXB + 2 * NWB, 256>>>(
        (const float4*)x,    (ushort4*)x16,
        (const float4*)Wq,   (ushort4*)wq16,
        (const float4*)Wout, (ushort4*)wo16);

    // K/V projection + pack (fused)
    kv_proj_pack<<<dim3(NH, BB), 512>>>(ctx,
        (const float*)d_in[5], (const float*)d_in[6],
        (const float*)d_in[7], (const float*)d_in[8], nimg);

    // Q projection (fp16 HMMA, pre-scaled by 1/sqrt(64)) -> swizzled fp16 Q tiles
    gemm_fp16<true, false><<<dim3(INNER / 128, (BB * SQ) / 128), 256, GEMM_SMEM>>>(
        x16, wq16, nullptr, nullptr, QD);

    // fp16 flash attention (register-lean v4) -> fp16
    attn_mma<<<dim3(BB * NH, SQ / 128), 128, ATTN_SMEM>>>(scale, nimg);

    // output projection + bias (fp16 HMMA)
    gemm_fp16<false, true><<<dim3(QD / 128, (BB * SQ) / 128), 256, GEMM_SMEM>>>(
        a16, wo16, bout, out, INNER);
}

// round 17
// speedup vs baseline: 1.0029x; 1.0029x over previous
#include <cuda_runtime.h>
#include <cuda_bf16.h>
#include <cuda_fp16.h>
#include <cstdint>
#include <cstddef>

// Problem constants
#define BB    8
#define SQ    4096
#define QD    1280
#define SCTX  93
#define CD    2048
#define NH    20
#define DH    64
#define INNER 1280

// ---------------------------------------------------------------------------
// Scratch (__device__ globals; no allocs allowed)
// ---------------------------------------------------------------------------
__device__ __align__(16) unsigned char g_qt[(size_t)BB * NH * 32 * 16384];
__device__ __align__(16) unsigned char g_kt[(size_t)BB * NH * 12288];
__device__ __align__(16) unsigned char g_vt[(size_t)BB * NH * 13312];

__device__ __half g_x16 [(size_t)BB * SQ * QD];
__device__ __half g_a16 [(size_t)BB * SQ * INNER];
__device__ __half g_wq16[(size_t)INNER * QD];
__device__ __half g_wo16[(size_t)QD * INNER];
__device__ float  g_k[(size_t)BB * NH * SCTX * DH];
__device__ float  g_v[(size_t)BB * NH * SCTX * DH];

// ---------------------------------------------------------------------------
// Helpers (arch-agnostic PTX only: cp.async, ldmatrix, mma.sync)
// ---------------------------------------------------------------------------
__device__ __forceinline__ uint32_t smem_u32(const void* p) {
    uint32_t a;
    asm("{ .reg .u64 t; cvta.to.shared.u64 t, %1; cvt.u32.u64 %0, t; }"
        : "=r"(a) : "l"(p));
    return a;
}
#define CP_COMMIT() asm volatile("cp.async.commit_group;" ::: "memory")
#define CP_WAIT(n)  asm volatile("cp.async.wait_group %0;" :: "n"(n) : "memory")
#define CP_ASYNC16(dst, src) \
    asm volatile("cp.async.cg.shared.global [%0], [%1], 16;" \
                 :: "r"(dst), "l"(src) : "memory")

__device__ __forceinline__ void ldsm_x4(uint32_t addr, uint32_t& r0, uint32_t& r1,
                                        uint32_t& r2, uint32_t& r3) {
    asm volatile("ldmatrix.sync.aligned.m8n8.x4.shared.b16 {%0,%1,%2,%3}, [%4];"
                 : "=r"(r0), "=r"(r1), "=r"(r2), "=r"(r3) : "r"(addr));
}
__device__ __forceinline__ void mma_fp16(float* c, const uint32_t* a,
                                         const uint32_t* b) {
    asm volatile(
        "mma.sync.aligned.m16n8k16.row.col.f32.f16.f16.f32 "
        "{%0,%1,%2,%3}, {%4,%5,%6,%7}, {%8,%9}, {%0,%1,%2,%3};"
        : "+f"(c[0]), "+f"(c[1]), "+f"(c[2]), "+f"(c[3])
        : "r"(a[0]), "r"(a[1]), "r"(a[2]), "r"(a[3]), "r"(b[0]), "r"(b[1]));
}
__device__ __forceinline__ uint32_t packhf(float x, float y) {
    __half2 t = __floats2half2_rn(x, y);
    return *(uint32_t*)&t;
}

// ---------------------------------------------------------------------------
// Single-launch fp32 -> fp16 cast for x, Wq, Wout (block-range dispatch)
// ---------------------------------------------------------------------------
#define NXB 4096
#define NWB 200
__global__ void __launch_bounds__(256) to_fp16_all(
    const float4* __restrict__ x,  ushort4* __restrict__ x16,
    const float4* __restrict__ wq, ushort4* __restrict__ wq16,
    const float4* __restrict__ wo, ushort4* __restrict__ wo16)
{
    const float4* src;
    ushort4* dst;
    int n4, bid, nb;
    if (blockIdx.x < NXB) {
        src = x;  dst = x16;  n4 = (int)((size_t)BB * SQ * QD / 4);
        bid = blockIdx.x; nb = NXB;
    } else if (blockIdx.x < NXB + NWB) {
        src = wq; dst = wq16; n4 = INNER * QD / 4;
        bid = blockIdx.x - NXB; nb = NWB;
    } else {
        src = wo; dst = wo16; n4 = QD * INNER / 4;
        bid = blockIdx.x - NXB - NWB; nb = NWB;
    }
    for (int i = bid * 256 + threadIdx.x; i < n4; i += nb * 256) {
        float4 v = src[i];
        ushort4 o;
        o.x = __half_as_ushort(__float2half_rn(v.x));
        o.y = __half_as_ushort(__float2half_rn(v.y));
        o.z = __half_as_ushort(__float2half_rn(v.z));
        o.w = __half_as_ushort(__float2half_rn(v.w));
        dst[i] = o;
    }
}

// ---------------------------------------------------------------------------
// KV projection + pack, fused (validated in R11-R16).
// ---------------------------------------------------------------------------
__global__ void __launch_bounds__(512) kv_proj_pack(
    const float* __restrict__ ctx,
    const float* __restrict__ Wk,  const float* __restrict__ Wv,
    const float* __restrict__ Wki, const float* __restrict__ Wvi,
    const int*   __restrict__ nimg_p)
{
    __shared__ float cs[96][17];
    __shared__ float wk_s[64][17], wv_s[64][17], wki_s[64][17], wvi_s[64][17];

    const int tid = threadIdx.x;
    const int b   = blockIdx.y;
    const int hh  = blockIdx.x;
    const int n0  = hh * 64;
    const int eos = SCTX - *nimg_p;
    const int n   = tid & 63;
    const int g   = tid >> 6;
    const int bh  = b * NH + hh;

    float ak[12], av[12];
#pragma unroll
    for (int j = 0; j < 12; ++j) { ak[j] = 0.f; av[j] = 0.f; }

    for (int k0 = 0; k0 < CD; k0 += 16) {
        __syncthreads();
        for (int i = tid; i < 96 * 16; i += 512) {
            int s = i >> 4, kk = i & 15;
            cs[s][kk] = (s < SCTX) ? ctx[((size_t)b * SCTX + s) * CD + k0 + kk] : 0.f;
        }
        for (int i = tid; i < 64 * 16; i += 512) {
            int r = i >> 4, kk = i & 15;
            size_t gi = (size_t)(n0 + r) * CD + k0 + kk;
            wk_s [r][kk] = Wk [gi]; wv_s [r][kk] = Wv [gi];
            wki_s[r][kk] = Wki[gi]; wvi_s[r][kk] = Wvi[gi];
        }
        __syncthreads();
#pragma unroll
        for (int kk = 0; kk < 16; ++kk) {
            float wkv = wk_s[n][kk],  wvv = wv_s[n][kk];
            float wkiv = wki_s[n][kk], wviv = wvi_s[n][kk];
#pragma unroll
            for (int j = 0; j < 12; ++j) {
                int s = g * 12 + j;
                float c = cs[s][kk];
                bool txt = (s < eos);
                ak[j] = fmaf(c, txt ? wkv : wkiv, ak[j]);
                av[j] = fmaf(c, txt ? wvv : wviv, av[j]);
            }
        }
    }
    size_t base = ((size_t)bh * SCTX) * DH + n;
#pragma unroll
    for (int j = 0; j < 12; ++j) {
        int s = g * 12 + j;
        if (s < SCTX) {
            g_k[base + (size_t)s * DH] = ak[j];
            g_v[base + (size_t)s * DH] = av[j];
        }
    }
    __syncthreads();

    // pack K: 96 rows x 128B swizzled fp16
    for (int idx = tid; idx < 96 * 8; idx += 512) {
        int r = idx >> 3, cb = idx & 7;
        float4 u = {0,0,0,0}, v = {0,0,0,0};
        if (r < SCTX) {
            const float4* kp = (const float4*)(g_k + ((size_t)bh * SCTX + r) * DH + cb * 8);
            u = kp[0]; v = kp[1];
        }
        uint4 H;
        H.x = packhf(u.x, u.y); H.y = packhf(u.z, u.w);
        H.z = packhf(v.x, v.y); H.w = packhf(v.z, v.w);
        size_t off = (size_t)bh * 12288 + r * 128 + ((cb ^ (r & 7)) << 4);
        *(uint4*)(g_kt + off) = H;
    }
    // pack Vt: 64 rows(d) x 208B stride fp16
    for (int idx = tid; idx < 64 * 12; idx += 512) {
        int d = idx / 12, sc = idx % 12;
        float vals[8];
#pragma unroll
        for (int j = 0; j < 8; ++j) {
            int s = sc * 8 + j;
            vals[j] = (s < SCTX) ? g_v[((size_t)bh * SCTX + s) * DH + d] : 0.f;
        }
        uint4 H;
        H.x = packhf(vals[0], vals[1]); H.y = packhf(vals[2], vals[3]);
        H.z = packhf(vals[4], vals[5]); H.w = packhf(vals[6], vals[7]);
        size_t off = (size_t)bh * 13312 + d * 208 + sc * 16;
        *(uint4*)(g_vt + off) = H;
    }
}

// ---------------------------------------------------------------------------
// fp16 HMMA GEMM (R8 config; REMAP_Q epilogue pre-scales Q by 1/sqrt(64)).
// ---------------------------------------------------------------------------
#define GEMM_STAGES 3
#define TILE_BYTES  16384
#define STAGE_BYTES (2 * TILE_BYTES)
#define GEMM_SMEM   (GEMM_STAGES * STAGE_BYTES)

__device__ __forceinline__ void load_tiles16(
    uint32_t sbase,
    const __half* __restrict__ A, const __half* __restrict__ B,
    int m0, int n0, int k0, int K, int tid)
{
#pragma unroll
    for (int i = 0; i < 8; ++i) {
        int idx = tid + (i << 8);
        int mat = idx >> 10;
        int r   = (idx >> 3) & 127;
        int cb  = idx & 7;
        int grow = ((mat == 0) ? m0 : n0) + r;
        const __half* base = (mat == 0) ? A : B;
        const char* src = (const char*)(base + (size_t)grow * K + k0) + (cb << 4);
        uint32_t dst = sbase + (mat << 14) + (r << 7)
                     + (uint32_t)((cb ^ (r & 7)) << 4);
        CP_ASYNC16(dst, src);
    }
}

template <bool REMAP_Q, bool HAS_BIAS>
__global__ void __launch_bounds__(256, 2) gemm_fp16(
    const __half* __restrict__ A, const __half* __restrict__ B,
    const float* __restrict__ bias, float* __restrict__ C, int K)
{
    extern __shared__ __align__(128) char smem[];
    const uint32_t sb = smem_u32(smem);
    const int tid  = threadIdx.x;
    const int wid  = tid >> 5;
    const int lane = tid & 31;
    const int mw   = wid >> 2;
    const int nw   = wid & 3;
    const int n0   = blockIdx.x << 7;
    const int m0   = blockIdx.y << 7;
    const int NCH  = K >> 6;

    uint32_t arow[4];
#pragma unroll
    for (int mi = 0; mi < 4; ++mi)
        arow[mi] = (uint32_t)(mw * 64 + mi * 16 + (lane & 15));
    uint32_t brow[2];
#pragma unroll
    for (int bt = 0; bt < 2; ++bt)
        brow[bt] = (uint32_t)(nw * 32 + bt * 16 + ((lane >> 4) << 3) + (lane & 7));
    const uint32_t cA = (uint32_t)(lane >> 4) << 4;
    const uint32_t cB = ((uint32_t)(lane >> 3) & 1) << 4;

    float acc[4][4][4];
#pragma unroll
    for (int i = 0; i < 4; ++i)
#pragma unroll
        for (int j = 0; j < 4; ++j)
#pragma unroll
            for (int v = 0; v < 4; ++v) acc[i][j][v] = 0.f;

#pragma unroll
    for (int c = 0; c < GEMM_STAGES - 1; ++c) {
        load_tiles16(sb + c * STAGE_BYTES, A, B, m0, n0, c << 6, K, tid);
        CP_COMMIT();
    }

    int s = 0;
    for (int c = 0; c < NCH; ++c) {
        CP_WAIT(1);
        __syncthreads();

        if (c + GEMM_STAGES - 1 < NCH) {
            int sn = c + GEMM_STAGES - 1;
            load_tiles16(sb + (sn % GEMM_STAGES) * STAGE_BYTES, A, B,
                         m0, n0, sn << 6, K, tid);
        }
        CP_COMMIT();

        const uint32_t bA = sb + s * STAGE_BYTES;
        const uint32_t bB = bA + TILE_BYTES;

#pragma unroll
        for (int t = 0; t < 4; ++t) {
            uint32_t a[4][4], b[4][2];
#pragma unroll
            for (int mi = 0; mi < 4; ++mi) {
                uint32_t byte = arow[mi] * 128
                    + (((uint32_t)(t * 32) + cA) ^ ((arow[mi] & 7) << 4));
                ldsm_x4(bA + byte, a[mi][0], a[mi][1], a[mi][2], a[mi][3]);
            }
#pragma unroll
            for (int bt = 0; bt < 2; ++bt) {
                uint32_t byte = brow[bt] * 128
                    + (((uint32_t)(t * 32) + cB) ^ ((brow[bt] & 7) << 4));
                ldsm_x4(bB + byte, b[bt*2][0], b[bt*2][1],
                                   b[bt*2+1][0], b[bt*2+1][1]);
            }
#pragma unroll
            for (int mi = 0; mi < 4; ++mi)
#pragma unroll
                for (int ni = 0; ni < 4; ++ni)
                    mma_fp16(acc[mi][ni], a[mi], b[ni]);
        }
        s = (s == GEMM_STAGES - 1) ? 0 : s + 1;
    }

    // epilogue
#pragma unroll
    for (int mi = 0; mi < 4; ++mi) {
        const int mbase = m0 + mw * 64 + mi * 16 + (lane >> 2);
#pragma unroll
        for (int ni = 0; ni < 4; ++ni) {
            const int n = n0 + nw * 32 + ni * 8 + (lane & 3) * 2;
            if (REMAP_Q) {
                const int h = n >> 6, d = n & 63;
#pragma unroll
                for (int rr = 0; rr < 2; ++rr) {
                    const int m  = mbase + rr * 8;
                    const int b_ = m >> 12, sq = m & 4095;
                    const int qt = sq >> 7,  r  = sq & 127;
                    const int bh = b_ * NH + h;
                    size_t off = ((size_t)(bh * 32 + qt)) * 16384
                               + r * 128 + (((d >> 3) ^ (r & 7)) << 4)
                               + (d & 7) * 2;
                    *(uint32_t*)(g_qt + off) =
                        packhf(acc[mi][ni][rr * 2] * 0.125f,
                               acc[mi][ni][rr * 2 + 1] * 0.125f);
                }
            } else {
                float2 v0, v1;
                v0.x = acc[mi][ni][0]; v0.y = acc[mi][ni][1];
                v1.x = acc[mi][ni][2]; v1.y = acc[mi][ni][3];
                if (HAS_BIAS) {
                    float b0 = bias[n], b1 = bias[n + 1];
                    v0.x += b0; v0.y += b1; v1.x += b0; v1.y += b1;
                }
                *(float2*)(C + (size_t)mbase * QD + n) = v0;
                *(float2*)(C + (size_t)(mbase + 8) * QD + n) = v1;
            }
        }
    }
}

// ---------------------------------------------------------------------------
// fp16 flash attention, register-lean v3 (R15 best config):
// - sequential m-tiles, interleaved ldsm/MMA
// - Q prescaled by 1/sqrt(64) in the GEMM epilogue
// - single-exp softmax: mask+max, one exp pass storing into Lg, scale pass.
// ---------------------------------------------------------------------------
#define AQ  0
#define AK  16384
#define AV  28672
#define ATTN_SMEM 41984

__global__ void __launch_bounds__(128, 5) attn_mma(
    const float* __restrict__ scale_p, const int* __restrict__ nimg_p)
{
    extern __shared__ __align__(128) char smem[];
    const uint32_t sb = smem_u32(smem);
    const int tid  = threadIdx.x;
    const int lane = tid & 31;
    const int w    = tid >> 5;
    const int bh   = blockIdx.x;
    const int qt   = blockIdx.y;
    const int q0   = qt << 7;
    const int b    = bh / NH;
    const int h    = bh % NH;
    const int eos  = SCTX - *nimg_p;
    const float ipscale = *scale_p;

    {
        const unsigned char* qb = g_qt + ((size_t)(bh * 32 + qt)) * 16384;
        for (uint32_t o = tid * 16; o < 16384; o += 2048)
            CP_ASYNC16(sb + AQ + o, qb + o);
        const unsigned char* kb = g_kt + (size_t)bh * 12288;
        for (uint32_t o = tid * 16; o < 12288; o += 2048)
            CP_ASYNC16(sb + AK + o, kb + o);
        const unsigned char* vb = g_vt + (size_t)bh * 13312;
        for (uint32_t o = tid * 16; o < 13312; o += 2048)
            CP_ASYNC16(sb + AV + o, vb + o);
    }
    CP_COMMIT();
    CP_WAIT(0);
    __syncthreads();

    const int c0 = 2 * (lane & 3);

#pragma unroll
    for (int mi = 0; mi < 2; ++mi) {
        // ---- QK^T for this 16-row tile (ldsm interleaved with MMA) ----
        float Lg[12][4];
#pragma unroll
        for (int j = 0; j < 12; ++j)
#pragma unroll
            for (int v = 0; v < 4; ++v) Lg[j][v] = 0.f;

#pragma unroll
        for (int kc = 0; kc < 4; ++kc) {
            uint32_t qa[4];
            {
                uint32_t row = (uint32_t)(w * 32 + mi * 16 + (lane & 15));
                uint32_t byte = row * 128
                    + (((uint32_t)(kc * 32) + ((uint32_t)(lane >> 4) << 4))
                       ^ ((row & 7) << 4));
                ldsm_x4(sb + AQ + byte, qa[0], qa[1], qa[2], qa[3]);
            }
#pragma unroll
            for (int bt = 0; bt < 6; ++bt) {
                uint32_t row = (uint32_t)(bt * 16 + ((lane >> 4) << 3) + (lane & 7));
                uint32_t byte = row * 128
                    + (((uint32_t)(kc * 32) + (((uint32_t)(lane >> 3) & 1) << 4))
                       ^ ((row & 7) << 4));
                uint32_t k0a, k0b, k1a, k1b;
                ldsm_x4(sb + AK + byte, k0a, k0b, k1a, k1b);
                uint32_t kb0[2] = {k0a, k0b};
                uint32_t kb1[2] = {k1a, k1b};
                mma_fp16(Lg[bt * 2],     qa, kb0);
                mma_fp16(Lg[bt * 2 + 1], qa, kb1);
            }
        }

        // ---- two-segment softmax (single-exp) ----
#pragma unroll
        for (int half = 0; half < 2; ++half) {
            // pass A: mask invalid cols to -1e30, find segment maxes
            float mx1 = -1e30f, mx2 = -1e30f;
#pragma unroll
            for (int j = 0; j < 12; ++j)
#pragma unroll
                for (int u = 0; u < 2; ++u) {
                    int col = j * 8 + c0 + u;
                    float v = Lg[j][half * 2 + u];
                    if (col >= SCTX) { v = -1e30f; Lg[j][half * 2 + u] = v; }
                    if (col < eos) mx1 = fmaxf(mx1, v);
                    else           mx2 = fmaxf(mx2, v);
                }
            mx1 = fmaxf(mx1, __shfl_xor_sync(0xffffffffu, mx1, 1));
            mx1 = fmaxf(mx1, __shfl_xor_sync(0xffffffffu, mx1, 2));
            mx2 = fmaxf(mx2, __shfl_xor_sync(0xffffffffu, mx2, 1));
            mx2 = fmaxf(mx2, __shfl_xor_sync(0xffffffffu, mx2, 2));
            // pass B: e = exp(v - mx_sel) once; store into Lg; accumulate sums
            float s1 = 0.f, s2 = 0.f;
#pragma unroll
            for (int j = 0; j < 12; ++j)
#pragma unroll
                for (int u = 0; u < 2; ++u) {
                    int col = j * 8 + c0 + u;
                    bool t = (col < eos);
                    float e = __expf(Lg[j][half * 2 + u] - (t ? mx1 : mx2));
                    Lg[j][half * 2 + u] = e;
                    if (t) s1 += e; else s2 += e;
                }
            s1 += __shfl_xor_sync(0xffffffffu, s1, 1);
            s1 += __shfl_xor_sync(0xffffffffu, s1, 2);
            s2 += __shfl_xor_sync(0xffffffffu, s2, 1);
            s2 += __shfl_xor_sync(0xffffffffu, s2, 2);
            float w1 = (s1 > 0.f) ? 1.f / s1 : 0.f;
            float w2 = (s2 > 0.f) ? ipscale / s2 : 0.f;
            // pass C: scale stored exps by segment weight
#pragma unroll
            for (int j = 0; j < 12; ++j)
#pragma unroll
                for (int u = 0; u < 2; ++u) {
                    int col = j * 8 + c0 + u;
                    Lg[j][half * 2 + u] *= (col < eos) ? w1 : w2;
                }
        }

        // ---- P * V for this tile (ldsm interleaved with MMA) ----
        float o[8][4];
#pragma unroll
        for (int nd = 0; nd < 8; ++nd)
#pragma unroll
            for (int v = 0; v < 4; ++v) o[nd][v] = 0.f;

#pragma unroll
        for (int kc = 0; kc < 6; ++kc) {
            const float* p0 = Lg[2 * kc];
            const float* p1 = Lg[2 * kc + 1];
            uint32_t pa[4];
            pa[0] = packhf(p0[0], p0[1]);
            pa[1] = packhf(p0[2], p0[3]);
            pa[2] = packhf(p1[0], p1[1]);
            pa[3] = packhf(p1[2], p1[3]);
#pragma unroll
            for (int dt = 0; dt < 4; ++dt) {
                uint32_t row = (uint32_t)(dt * 16 + ((lane >> 4) << 3) + (lane & 7));
                uint32_t byte = row * 208 + (uint32_t)(kc * 32)
                              + (((uint32_t)(lane >> 3) & 1) << 4);
                uint32_t v0a, v0b, v1a, v1b;
                ldsm_x4(sb + AV + byte, v0a, v0b, v1a, v1b);
                uint32_t vb0[2] = {v0a, v0b};
                uint32_t vb1[2] = {v1a, v1b};
                mma_fp16(o[dt * 2],     pa, vb0);
                mma_fp16(o[dt * 2 + 1], pa, vb1);
            }
        }

        // ---- store this tile ----
        const int r0 = q0 + w * 32 + mi * 16 + (lane >> 2);
#pragma unroll
        for (int nd = 0; nd < 8; ++nd) {
            const int d = nd * 8 + c0;
            size_t base0 = ((size_t)b * SQ + r0) * INNER + h * DH + d;
            size_t base1 = base0 + (size_t)8 * INNER;
            *(uint32_t*)(g_a16 + base0) = packhf(o[nd][0], o[nd][1]);
            *(uint32_t*)(g_a16 + base1) = packhf(o[nd][2], o[nd][3]);
        }
    }
}

// ---------------------------------------------------------------------------
// Launch: x, context, scale, num_img_token, Wq, Wk, Wv, Wk_ip, Wv_ip, Wout, b_out
// ---------------------------------------------------------------------------
extern "C" void kernel_launch(void* const* d_in, const int* in_sizes, int n_in,
                              void* d_out, int out_size)
{
    const float* x     = (const float*)d_in[0];
    const float* ctx   = (const float*)d_in[1];
    const float* scale = (const float*)d_in[2];
    const int*   nimg  = (const int*)  d_in[3];
    const float* Wq    = (const float*)d_in[4];
    const float* Wout  = (const float*)d_in[9];
    const float* bout  = (const float*)d_in[10];
    float*       out   = (float*)d_out;

    __half *x16, *a16, *wq16, *wo16;
    cudaGetSymbolAddress((void**)&x16,  g_x16);
    cudaGetSymbolAddress((void**)&a16,  g_a16);
    cudaGetSymbolAddress((void**)&wq16, g_wq16);
    cudaGetSymbolAddress((void**)&wo16, g_wo16);

    cudaFuncSetAttribute(attn_mma,
        cudaFuncAttributeMaxDynamicSharedMemorySize, ATTN_SMEM);
    cudaFuncSetAttribute(gemm_fp16<true, false>,
        cudaFuncAttributeMaxDynamicSharedMemorySize, GEMM_SMEM);
    cudaFuncSetAttribute(gemm_fp16<false, true>,
        cudaFuncAttributeMaxDynamicSharedMemorySize, GEMM_SMEM);

    // conversions (single launch for x, Wq, Wout)
    to_fp16_all<<<NXB + 2 * NWB, 256>>>(
        (const float4*)x,    (ushort4*)x16,
        (const float4*)Wq,   (ushort4*)wq16,
        (const float4*)Wout, (ushort4*)wo16);

    // K/V projection + pack (fused)
    kv_proj_pack<<<dim3(NH, BB), 512>>>(ctx,
        (const float*)d_in[5], (const float*)d_in[6],
        (const float*)d_in[7], (const float*)d_in[8], nimg);

    // Q projection (fp16 HMMA, pre-scaled by 1/sqrt(64)) -> swizzled fp16 Q tiles
    gemm_fp16<true, false><<<dim3(INNER / 128, (BB * SQ) / 128), 256, GEMM_SMEM>>>(
        x16, wq16, nullptr, nullptr, QD);

    // fp16 flash attention (register-lean v3, single-exp softmax) -> fp16
    attn_mma<<<dim3(BB * NH, SQ / 128), 128, ATTN_SMEM>>>(scale, nimg);

    // output projection + bias (fp16 HMMA)
    gemm_fp16<false, true><<<dim3(QD / 128, (BB * SQ) / 128), 256, GEMM_SMEM>>>(
        a16, wo16, bout, out, INNER);
}